// round 9
// baseline (speedup 1.0000x reference)
#include <cuda_runtime.h>
#include <cstdint>

#define BB    256
#define LL    512
#define DD    64
#define NID   10000
#define TROWS 8      // table rows; counts >= 8 take the (never-hit) uniform cold path

// ---------------------------------------------------------------------------
// One CTA per batch, 1024 threads. Lower 512 threads own the src sequence,
// upper 512 own the dst sequence (1 id load + 1 atomic + 16 store iters each).
// Packed smem histogram: lo16 = count of id in src seq, hi16 = count in dst.
// 8x64 g-table built concurrently with the atomics phase.
// 46.9 KB static smem + <=32 regs -> 2 CTAs/SM -> 2048 threads/SM (full occ).
// ---------------------------------------------------------------------------
__global__ void __launch_bounds__(1024, 2) fused_encode(
        const int* __restrict__ src,
        const int* __restrict__ dst,
        const float* __restrict__ W1,
        const float* __restrict__ b1,
        const float* __restrict__ W2,
        const float* __restrict__ b2,
        float* __restrict__ out) {
    __shared__ __align__(16) uint32_t hist[NID];          // 40000 B
    __shared__ __align__(16) float    table[TROWS * DD];  //  2048 B
    __shared__ __align__(16) uint32_t cs[LL];             //  2048 B
    __shared__ __align__(16) uint32_t cd[LL];             //  2048 B
    __shared__ float w1s[DD], b1s[DD], b2s[DD];           //   768 B
    __shared__ uint32_t maxc;

    const int t    = threadIdx.x;
    const int half = t >> 9;        // 0 = src role, 1 = dst role
    const int tt   = t & 511;       // position within the sequence
    const int b    = blockIdx.x;

    // ---- P0: zero histogram (128-bit), stage params, load own id ----
    const uint4 z = make_uint4(0u, 0u, 0u, 0u);
    #pragma unroll
    for (int i = t; i < NID / 4; i += 1024) ((uint4*)hist)[i] = z;
    if (t < DD)            w1s[t]          = W1[t];
    else if (t < 2 * DD)   b1s[t - DD]     = b1[t - DD];
    else if (t < 3 * DD)   b2s[t - 2 * DD] = b2[t - 2 * DD];
    if (t == 0) maxc = 0u;

    const int* ids = half ? dst : src;
    const int myid = ids[b * LL + tt];
    __syncthreads();

    // ---- P1: packed dual histogram + (concurrently) 8x64 table build ----
    atomicAdd(&hist[myid], half ? 0x10000u : 1u);
    if (t < TROWS * DD) {
        const int a = t >> 6, e = t & 63;    // threads 0..511: 8 rows x 64 cols
        const float fa = (float)a;
        float s = b2s[e];
        const float4* w2r4 = (const float4*)(W2 + e * DD);
        #pragma unroll 4
        for (int j = 0; j < 16; ++j) {
            const float4 w4 = __ldg(&w2r4[j]);
            const int d = j * 4;
            const float h0 = fmaxf(fmaf(fa, w1s[d + 0], b1s[d + 0]), 0.f);
            const float h1 = fmaxf(fmaf(fa, w1s[d + 1], b1s[d + 1]), 0.f);
            const float h2 = fmaxf(fmaf(fa, w1s[d + 2], b1s[d + 2]), 0.f);
            const float h3 = fmaxf(fmaf(fa, w1s[d + 3], b1s[d + 3]), 0.f);
            s = fmaf(h0, w4.x, s);
            s = fmaf(h1, w4.y, s);
            s = fmaf(h2, w4.z, s);
            s = fmaf(h3, w4.w, s);
        }
        table[t] = s;
    }
    __syncthreads();

    // ---- P2: per-position packed count for own role (id 0 -> (0,0)); max ----
    const uint32_t c = myid ? hist[myid] : 0u;
    (half ? cd : cs)[tt] = c;
    uint32_t m = max(c & 0xFFFFu, c >> 16);
    m = __reduce_max_sync(0xFFFFFFFFu, m);
    if ((t & 31) == 0) atomicMax(&maxc, m);
    __syncthreads();

    // ---- P3: store. Each half streams its 512 rows x 256 B. ----
    const int lane = tt & 15;
    const uint32_t* __restrict__ cc = half ? cd : cs;
    float4* __restrict__ o =
        (float4*)(out + ((size_t)half * BB + b) * LL * DD);

    if (maxc < TROWS) {
        const float4* __restrict__ T4 = (const float4*)table;
        #pragma unroll 4
        for (int r = (tt >> 4); r < LL; r += 32) {
            const uint32_t cr = cc[r];
            const float4 v0 = T4[(cr & 0xFFFFu) * 16 + lane];
            const float4 v1 = T4[(cr >> 16)     * 16 + lane];
            float4 w;
            w.x = v0.x + v1.x; w.y = v0.y + v1.y;
            w.z = v0.z + v1.z; w.w = v0.w + v1.w;
            o[r * 16 + lane] = w;
        }
    } else {
        // CTA-uniform cold path (never taken with this data): direct compute.
        for (int r = (tt >> 4); r < LL; r += 32) {
            const uint32_t cr = cc[r];
            const float a0 = (float)(cr & 0xFFFFu);
            const float a1 = (float)(cr >> 16);
            float4 s;
            s.x = 2.f * b2s[lane * 4 + 0];
            s.y = 2.f * b2s[lane * 4 + 1];
            s.z = 2.f * b2s[lane * 4 + 2];
            s.w = 2.f * b2s[lane * 4 + 3];
            for (int d = 0; d < DD; ++d) {
                const float h = fmaxf(fmaf(a0, w1s[d], b1s[d]), 0.f)
                              + fmaxf(fmaf(a1, w1s[d], b1s[d]), 0.f);
                s.x = fmaf(h, __ldg(&W2[(lane * 4 + 0) * DD + d]), s.x);
                s.y = fmaf(h, __ldg(&W2[(lane * 4 + 1) * DD + d]), s.y);
                s.z = fmaf(h, __ldg(&W2[(lane * 4 + 2) * DD + d]), s.z);
                s.w = fmaf(h, __ldg(&W2[(lane * 4 + 3) * DD + d]), s.w);
            }
            o[r * 16 + lane] = s;
        }
    }
}

// ---------------------------------------------------------------------------
// Inputs: 0 src_ids, 1 dst_ids, 2 W1(D,1), 3 b1(D), 4 W2(D,D), 5 b2(D)
// Output: [src_feat | dst_feat], each B*L*D f32.
// ---------------------------------------------------------------------------
extern "C" void kernel_launch(void* const* d_in, const int* in_sizes, int n_in,
                              void* d_out, int out_size) {
    const int*   src = (const int*)d_in[0];
    const int*   dst = (const int*)d_in[1];
    const float* W1  = (const float*)d_in[2];
    const float* b1  = (const float*)d_in[3];
    const float* W2  = (const float*)d_in[4];
    const float* b2  = (const float*)d_in[5];
    float* out = (float*)d_out;

    fused_encode<<<BB, 1024>>>(src, dst, W1, b1, W2, b2, out);
}

// round 10
// speedup vs baseline: 1.0596x; 1.0596x over previous
#include <cuda_runtime.h>
#include <cstdint>

#define BB    256
#define LL    512
#define DD    64
#define NID   10000
#define TROWS 8      // g-table rows; counts >= 8 take the (never-hit) uniform cold path

// dynamic smem layout (bytes):
//   [0     , 40000) hist : 10000 u32 packed (lo16 = cnt in src seq, hi16 = in dst)
//   [40000 , 56384) comb : 64 x 64 f32  combined rows g(a0)+g(a1), pair = a0+8*a1
//   [56384 , 58432) g8   : 8 x 64 f32   g(a) rows
//   [58432 , 62528) ofs  : 512 uint2    per-position float4-offsets (src, dst)
//   [62528 , 63296) w1s/b1s/b2s
//   [63296 , 63300) maxc
#define SM_HIST 0
#define SM_COMB 40000
#define SM_G8   56384
#define SM_OFS  58432
#define SM_W1   62528
#define SM_B1   62784
#define SM_B2   63040
#define SM_MAXC 63296
#define SMEM_BYTES 63312

__global__ void __launch_bounds__(512) fused_encode(
        const int* __restrict__ src,
        const int* __restrict__ dst,
        const float* __restrict__ W1,
        const float* __restrict__ b1,
        const float* __restrict__ W2,
        const float* __restrict__ b2,
        float* __restrict__ out) {
    extern __shared__ __align__(16) unsigned char sraw[];
    uint32_t* hist = (uint32_t*)(sraw + SM_HIST);
    float*    comb = (float*)(sraw + SM_COMB);
    float*    g8   = (float*)(sraw + SM_G8);
    uint2*    ofs  = (uint2*)(sraw + SM_OFS);
    float*    w1s  = (float*)(sraw + SM_W1);
    float*    b1s  = (float*)(sraw + SM_B1);
    float*    b2s  = (float*)(sraw + SM_B2);
    uint32_t* maxc = (uint32_t*)(sraw + SM_MAXC);

    const int t = threadIdx.x;
    const int b = blockIdx.x;

    // ---- P0: zero histogram (128-bit), stage params, load ids ----
    const uint4 z = make_uint4(0u, 0u, 0u, 0u);
    #pragma unroll
    for (int i = t; i < NID / 4; i += 512) ((uint4*)hist)[i] = z;
    if (t < DD)            w1s[t]          = W1[t];
    else if (t < 2 * DD)   b1s[t - DD]     = b1[t - DD];
    else if (t < 3 * DD)   b2s[t - 2 * DD] = b2[t - 2 * DD];
    if (t == 0) *maxc = 0u;

    const int sid = src[b * LL + t];
    const int did = dst[b * LL + t];
    __syncthreads();

    // ---- P1: packed dual histogram + (concurrently) 8x64 g-table build ----
    atomicAdd(&hist[sid], 1u);
    atomicAdd(&hist[did], 0x10000u);
    {
        const int a = t >> 6, e = t & 63;      // 512 threads = 8 rows x 64 cols
        const float fa = (float)a;
        float s = b2s[e];
        const float4* w2r4 = (const float4*)(W2 + e * DD);
        #pragma unroll 4
        for (int j = 0; j < 16; ++j) {
            const float4 w4 = __ldg(&w2r4[j]);
            const int d = j * 4;
            const float h0 = fmaxf(fmaf(fa, w1s[d + 0], b1s[d + 0]), 0.f);
            const float h1 = fmaxf(fmaf(fa, w1s[d + 1], b1s[d + 1]), 0.f);
            const float h2 = fmaxf(fmaf(fa, w1s[d + 2], b1s[d + 2]), 0.f);
            const float h3 = fmaxf(fmaf(fa, w1s[d + 3], b1s[d + 3]), 0.f);
            s = fmaf(h0, w4.x, s);
            s = fmaf(h1, w4.y, s);
            s = fmaf(h2, w4.z, s);
            s = fmaf(h3, w4.w, s);
        }
        g8[t] = s;
    }
    __syncthreads();

    // ---- P2: build 64-pair combined table + gather per-position offsets ----
    #pragma unroll
    for (int i = t; i < 64 * DD; i += 512) {
        const int e  = i & 63;
        const int a0 = (i >> 6) & 7;           // src-count (low)  -> first addend
        const int a1 = i >> 9;                 // dst-count (high) -> second addend
        comb[i] = g8[a0 * DD + e] + g8[a1 * DD + e];
    }
    const uint32_t hs = sid ? hist[sid] : 0u;  // padding id 0 -> (0,0)
    const uint32_t hd = did ? hist[did] : 0u;
    // float4 offset of the combined row: pair * 16
    const uint32_t po_s = (((hs & 0xFFFFu) + ((hs >> 16) << 3)) << 4);
    const uint32_t po_d = (((hd & 0xFFFFu) + ((hd >> 16) << 3)) << 4);
    ofs[t] = make_uint2(po_s, po_d);
    uint32_t m = max(max(hs & 0xFFFFu, hs >> 16), max(hd & 0xFFFFu, hd >> 16));
    m = __reduce_max_sync(0xFFFFFFFFu, m);
    if ((t & 31) == 0) atomicMax(maxc, m);
    __syncthreads();

    // ---- P3: store 512 KB. Hot loop: LDS.64 + 2x LDS.128 + 2x STG.128 per
    // (src row, dst row) pair. No arithmetic, minimal port traffic. ----
    const int lane = t & 15;
    float4* __restrict__ osrc = (float4*)(out + (size_t)b * LL * DD);
    float4* __restrict__ odst = (float4*)(out + ((size_t)BB + b) * LL * DD);

    if (*maxc < TROWS) {
        const float4* __restrict__ C4 = (const float4*)comb;
        #pragma unroll 4
        for (int r = (t >> 4); r < LL; r += 32) {
            const uint2 of = ofs[r];
            const float4 ws = C4[of.x + lane];
            const float4 wd = C4[of.y + lane];
            osrc[r * 16 + lane] = ws;
            odst[r * 16 + lane] = wd;
        }
    } else {
        // CTA-uniform cold path (never taken with this data): direct compute
        // from the (still intact) histogram, reloading ids from global.
        for (int r = (t >> 4); r < LL; r += 32) {
            const int sid2 = src[b * LL + r];
            const int did2 = dst[b * LL + r];
            const uint32_t csr = sid2 ? hist[sid2] : 0u;
            const uint32_t cdr = did2 ? hist[did2] : 0u;
            const float sa0 = (float)(csr & 0xFFFFu), sa1 = (float)(csr >> 16);
            const float da0 = (float)(cdr & 0xFFFFu), da1 = (float)(cdr >> 16);
            float4 accs, accd;
            accs.x = 2.f * b2s[lane * 4 + 0]; accd.x = accs.x;
            accs.y = 2.f * b2s[lane * 4 + 1]; accd.y = accs.y;
            accs.z = 2.f * b2s[lane * 4 + 2]; accd.z = accs.z;
            accs.w = 2.f * b2s[lane * 4 + 3]; accd.w = accs.w;
            for (int d = 0; d < DD; ++d) {
                const float hsum_s = fmaxf(fmaf(sa0, w1s[d], b1s[d]), 0.f)
                                   + fmaxf(fmaf(sa1, w1s[d], b1s[d]), 0.f);
                const float hsum_d = fmaxf(fmaf(da0, w1s[d], b1s[d]), 0.f)
                                   + fmaxf(fmaf(da1, w1s[d], b1s[d]), 0.f);
                accs.x = fmaf(hsum_s, __ldg(&W2[(lane*4+0)*DD + d]), accs.x);
                accs.y = fmaf(hsum_s, __ldg(&W2[(lane*4+1)*DD + d]), accs.y);
                accs.z = fmaf(hsum_s, __ldg(&W2[(lane*4+2)*DD + d]), accs.z);
                accs.w = fmaf(hsum_s, __ldg(&W2[(lane*4+3)*DD + d]), accs.w);
                accd.x = fmaf(hsum_d, __ldg(&W2[(lane*4+0)*DD + d]), accd.x);
                accd.y = fmaf(hsum_d, __ldg(&W2[(lane*4+1)*DD + d]), accd.y);
                accd.z = fmaf(hsum_d, __ldg(&W2[(lane*4+2)*DD + d]), accd.z);
                accd.w = fmaf(hsum_d, __ldg(&W2[(lane*4+3)*DD + d]), accd.w);
            }
            osrc[r * 16 + lane] = accs;
            odst[r * 16 + lane] = accd;
        }
    }
}

// ---------------------------------------------------------------------------
// Inputs: 0 src_ids, 1 dst_ids, 2 W1(D,1), 3 b1(D), 4 W2(D,D), 5 b2(D)
// Output: [src_feat | dst_feat], each B*L*D f32.
// ---------------------------------------------------------------------------
extern "C" void kernel_launch(void* const* d_in, const int* in_sizes, int n_in,
                              void* d_out, int out_size) {
    const int*   src = (const int*)d_in[0];
    const int*   dst = (const int*)d_in[1];
    const float* W1  = (const float*)d_in[2];
    const float* b1  = (const float*)d_in[3];
    const float* W2  = (const float*)d_in[4];
    const float* b2  = (const float*)d_in[5];
    float* out = (float*)d_out;

    cudaFuncSetAttribute(fused_encode,
                         cudaFuncAttributeMaxDynamicSharedMemorySize, SMEM_BYTES);
    fused_encode<<<BB, 512, SMEM_BYTES>>>(src, dst, W1, b1, W2, b2, out);
}